// round 3
// baseline (speedup 1.0000x reference)
#include <cuda_runtime.h>
#include <cuda_bf16.h>
#include <math.h>

#define DIMS 256
#define WIN 32
#define ROWS 33              // prev token + 32 window tokens
#define SIM_THR 0.7f

// fallback scratch if the harness output holds only `compressed`
__device__ float g_mask_scratch[262144];

__device__ __forceinline__ float warp_sum(float v) {
    #pragma unroll
    for (int o = 16; o; o >>= 1) v += __shfl_xor_sync(0xffffffffu, v, o);
    return v;
}

__global__ __launch_bounds__(256, 6)
void focus_kernel(const float* __restrict__ x,
                  float* __restrict__ mask_out,
                  float* __restrict__ comp_out,
                  int nw)
{
    __shared__ float sx[ROWS * DIMS];     // row 0 = prev window's last token
    __shared__ float s_invn[ROWS];
    __shared__ float s_S[DIMS];
    __shared__ float s_ms[WIN];
    __shared__ float s_m3[WIN];

    const int tid  = threadIdx.x;
    const int lane = tid & 31;
    const int wi   = tid >> 5;            // warp id 0..7
    const int w    = blockIdx.x;
    const int base = w * WIN;             // first global token of this window

    // ---- load 33 rows (float4) ----
    const float4* x4  = reinterpret_cast<const float4*>(x);
    float4*       sx4 = reinterpret_cast<float4*>(sx);
    const int gbase = (base - 1) * (DIMS / 4);          // row -1 start (float4 units)
    #pragma unroll
    for (int idx = tid; idx < ROWS * (DIMS / 4); idx += 256) {
        float4 v;
        if (w == 0 && idx < (DIMS / 4)) { v.x = v.y = v.z = v.w = 0.0f; }
        else                            { v = x4[gbase + idx]; }
        sx4[idx] = v;
    }
    __syncthreads();

    // ---- per-row inverse norms (warp per row) ----
    for (int r = wi; r < ROWS; r += 8) {
        const float* row = sx + r * DIMS;
        float ss = 0.0f;
        #pragma unroll
        for (int e = lane; e < DIMS; e += 32) { float v = row[e]; ss = fmaf(v, v, ss); }
        ss = warp_sum(ss);
        if (lane == 0) s_invn[r] = 1.0f / fmaxf(sqrtf(ss), 1e-12f);
    }
    __syncthreads();

    // ---- S[d] = sum over window tokens of xn[t][d] ----
    {
        float s = 0.0f;
        #pragma unroll
        for (int t = 1; t <= WIN; t++) s = fmaf(sx[t * DIMS + tid], s_invn[t], s);
        s_S[tid] = s;
    }
    __syncthreads();

    // ---- mean_sim[t] = invn[t] * dot(x_t, S) / 32  (warp per token) ----
    for (int t = wi; t < WIN; t += 8) {
        const float* row = sx + (t + 1) * DIMS;
        float d = 0.0f;
        #pragma unroll
        for (int e = lane; e < DIMS; e += 32) d = fmaf(row[e], s_S[e], d);
        d = warp_sum(d);
        if (lane == 0) s_ms[t] = d * s_invn[t + 1] * (1.0f / 32.0f);
    }
    __syncthreads();

    // ---- stage-1 keep decision: warp 0 only ----
    if (wi == 0) {
        float m = s_ms[lane];
        float sum = m, sq = m * m;
        #pragma unroll
        for (int o = 16; o; o >>= 1) {
            sum += __shfl_xor_sync(0xffffffffu, sum, o);
            sq  += __shfl_xor_sync(0xffffffffu, sq,  o);
        }
        float mu  = sum * (1.0f / 32.0f);
        float var = fmaxf((sq - 32.0f * mu * mu) * (1.0f / 31.0f), 0.0f);
        float thr = mu + sqrtf(var);
        bool keep = !(m > thr);
        unsigned bal = __ballot_sync(0xffffffffu, keep);
        if (bal == 0u) {
            // argmin fallback (first-min index, matching jnp.argmin)
            float vmin = m; int imin = lane;
            #pragma unroll
            for (int o = 16; o; o >>= 1) {
                float ov = __shfl_xor_sync(0xffffffffu, vmin, o);
                int   oi = __shfl_xor_sync(0xffffffffu, imin, o);
                if (ov < vmin || (ov == vmin && oi < imin)) { vmin = ov; imin = oi; }
            }
            keep = (lane == imin);
        }
        mask_out[base + lane] = keep ? 1.0f : 0.0f;
    }

    // ---- stage-3: adjacent-pair cosine -> mask3 (warp per pair) ----
    for (int r = wi; r < WIN; r += 8) {
        const float* a = sx + r * DIMS;          // token base+r-1
        const float* b = a + DIMS;               // token base+r
        float d = 0.0f;
        #pragma unroll
        for (int e = lane; e < DIMS; e += 32) d = fmaf(a[e], b[e], d);
        d = warp_sum(d);
        if (lane == 0) {
            bool m3 = (base + r == 0) ||
                      (d * s_invn[r] * s_invn[r + 1] < SIM_THR);
            s_m3[r] = m3 ? 1.0f : 0.0f;
        }
    }
    __syncthreads();

    // ---- write compressed = x * mask3 (float4) ----
    float4* c4 = reinterpret_cast<float4*>(comp_out);
    const int obase = base * (DIMS / 4);
    #pragma unroll
    for (int idx = tid; idx < WIN * (DIMS / 4); idx += 256) {
        int t = idx >> 6;                        // token within window
        float m = s_m3[t];
        float4 v = sx4[(t + 1) * (DIMS / 4) + (idx & 63)];
        v.x *= m; v.y *= m; v.z *= m; v.w *= m;
        c4[obase + idx] = v;
    }
}

extern "C" void kernel_launch(void* const* d_in, const int* in_sizes, int n_in,
                              void* d_out, int out_size)
{
    const float* x = (const float*)d_in[0];
    const int total = in_sizes[0];       // N * 256
    const int N  = total / DIMS;
    const int nw = N / WIN;
    float* out = (float*)d_out;

    float* mask_out;
    float* comp_out;
    if (out_size == N + total) {         // [mask1 (N) | compressed (N*D)]
        mask_out = out;
        comp_out = out + N;
    } else {                             // only compressed fits -> mask to scratch
        float* scratch;
        cudaGetSymbolAddress((void**)&scratch, g_mask_scratch);
        mask_out = scratch;
        comp_out = out;
    }

    focus_kernel<<<nw, 256>>>(x, mask_out, comp_out, nw);
}

// round 7
// speedup vs baseline: 1.4710x; 1.4710x over previous
#include <cuda_runtime.h>
#include <cuda_bf16.h>
#include <math.h>

#define DIMS 256
#define WIN 32
#define SIM_THR 0.7f

// fallback scratch if the harness output holds only `compressed`
__device__ float g_mask_scratch[262144];

__device__ __forceinline__ float warp_sum(float v) {
    #pragma unroll
    for (int o = 16; o; o >>= 1) v += __shfl_xor_sync(0xffffffffu, v, o);
    return v;
}

// Block = 256 threads = 8 warps; one 32-token window per block.
// Each warp owns 4 tokens; each lane holds 8 floats per row in registers:
//   regs j=0..3 <- float4 at x4[row*64 + lane]      (dims 4*lane   .. 4*lane+3)
//   regs j=4..7 <- float4 at x4[row*64 + 32 + lane] (dims 128+4*lane ..)
// All math is dot products / elementwise, so the fixed permutation is harmless.
__global__ __launch_bounds__(256)
void focus_kernel(const float4* __restrict__ x4,
                  float* __restrict__ mask_out,
                  float4* __restrict__ comp4)
{
    __shared__ float s_buf[8 * DIMS];   // partial S, then reused for boundary rows
    __shared__ float s_S[DIMS];
    __shared__ float s_invn[WIN];
    __shared__ float s_ms[WIN];

    const int lane = threadIdx.x & 31;
    const int wi   = threadIdx.x >> 5;
    const int w    = blockIdx.x;
    const int base = w * WIN;
    const int t0   = wi * 4;            // first window-token of this warp

    // ---- load 4 rows into registers (front-batched, coalesced float4) ----
    float v[4][8];
    #pragma unroll
    for (int k = 0; k < 4; k++) {
        const float4* row = x4 + (size_t)(base + t0 + k) * (DIMS / 4);
        float4 a = row[lane];
        float4 b = row[32 + lane];
        v[k][0] = a.x; v[k][1] = a.y; v[k][2] = a.z; v[k][3] = a.w;
        v[k][4] = b.x; v[k][5] = b.y; v[k][6] = b.z; v[k][7] = b.w;
    }

    // prev-window last row (only warp 0 uses it; zeros for the very first window)
    float pr[8] = {0.f, 0.f, 0.f, 0.f, 0.f, 0.f, 0.f, 0.f};
    if (wi == 0 && w != 0) {
        const float4* row = x4 + (size_t)(base - 1) * (DIMS / 4);
        float4 a = row[lane];
        float4 b = row[32 + lane];
        pr[0] = a.x; pr[1] = a.y; pr[2] = a.z; pr[3] = a.w;
        pr[4] = b.x; pr[5] = b.y; pr[6] = b.z; pr[7] = b.w;
    }

    // ---- per-row inverse norms (register dots + warp reduce) ----
    float invn[4];
    #pragma unroll
    for (int k = 0; k < 4; k++) {
        float ss = 0.0f;
        #pragma unroll
        for (int j = 0; j < 8; j++) ss = fmaf(v[k][j], v[k][j], ss);
        ss = warp_sum(ss);
        invn[k] = 1.0f / fmaxf(sqrtf(ss), 1e-12f);
        if (lane == 0) s_invn[t0 + k] = invn[k];
    }
    float invnP = 0.0f;                 // prev-row inv-norm (valid in warp 0)
    if (wi == 0) {
        float ss = 0.0f;
        #pragma unroll
        for (int j = 0; j < 8; j++) ss = fmaf(pr[j], pr[j], ss);
        ss = warp_sum(ss);
        invnP = 1.0f / fmaxf(sqrtf(ss), 1e-12f);
    }

    // ---- partial S (sum of normalized rows) per warp -> smem ----
    #pragma unroll
    for (int j = 0; j < 8; j++) {
        float ps = 0.0f;
        #pragma unroll
        for (int k = 0; k < 4; k++) ps = fmaf(v[k][j], invn[k], ps);
        s_buf[wi * DIMS + j * 32 + lane] = ps;
    }
    __syncthreads();

    // ---- cross-warp reduce of S (one dim-slot per thread) ----
    {
        const int t = threadIdx.x;
        float s = 0.0f;
        #pragma unroll
        for (int ww = 0; ww < 8; ww++) s += s_buf[ww * DIMS + t];
        s_S[t] = s;
    }
    __syncthreads();

    // ---- S into registers, mean_sim per token ----
    float Sr[8];
    #pragma unroll
    for (int j = 0; j < 8; j++) Sr[j] = s_S[j * 32 + lane];

    #pragma unroll
    for (int k = 0; k < 4; k++) {
        float d = 0.0f;
        #pragma unroll
        for (int j = 0; j < 8; j++) d = fmaf(v[k][j], Sr[j], d);
        d = warp_sum(d);
        if (lane == 0) s_ms[t0 + k] = d * invn[k] * (1.0f / 32.0f);
    }

    // ---- boundary-row exchange for stage-3 (reuse s_buf after its reads) ----
    #pragma unroll
    for (int j = 0; j < 8; j++) s_buf[wi * DIMS + j * 32 + lane] = v[3][j];
    __syncthreads();

    if (wi != 0) {
        #pragma unroll
        for (int j = 0; j < 8; j++) pr[j] = s_buf[(wi - 1) * DIMS + j * 32 + lane];
    }
    const float invnPrev = (wi == 0) ? invnP : s_invn[t0 - 1];

    // ---- stage-3: adjacent-pair cosine -> mask3 for this warp's 4 tokens ----
    float m3[4];
    #pragma unroll
    for (int k = 0; k < 4; k++) {
        float d = 0.0f;
        if (k == 0) {
            #pragma unroll
            for (int j = 0; j < 8; j++) d = fmaf(pr[j], v[0][j], d);
        } else {
            #pragma unroll
            for (int j = 0; j < 8; j++) d = fmaf(v[k - 1][j], v[k][j], d);
        }
        d = warp_sum(d);
        const float ipa = (k == 0) ? invnPrev : invn[k - 1];
        const bool keep = (base + t0 + k == 0) || (d * ipa * invn[k] < SIM_THR);
        m3[k] = keep ? 1.0f : 0.0f;
    }

    // ---- stage-1 keep decision (warp 0; s_ms is complete since last sync) ----
    if (wi == 0) {
        float m = s_ms[lane];
        float sum = m, sq = m * m;
        #pragma unroll
        for (int o = 16; o; o >>= 1) {
            sum += __shfl_xor_sync(0xffffffffu, sum, o);
            sq  += __shfl_xor_sync(0xffffffffu, sq,  o);
        }
        const float mu  = sum * (1.0f / 32.0f);
        const float var = fmaxf((sq - 32.0f * mu * mu) * (1.0f / 31.0f), 0.0f);
        bool keep = !(m > mu + sqrtf(var));
        const unsigned bal = __ballot_sync(0xffffffffu, keep);
        if (bal == 0u) {
            float vmin = m; int imin = lane;
            #pragma unroll
            for (int o = 16; o; o >>= 1) {
                const float ov = __shfl_xor_sync(0xffffffffu, vmin, o);
                const int   oi = __shfl_xor_sync(0xffffffffu, imin, o);
                if (ov < vmin || (ov == vmin && oi < imin)) { vmin = ov; imin = oi; }
            }
            keep = (lane == imin);
        }
        mask_out[base + lane] = keep ? 1.0f : 0.0f;
    }

    // ---- write compressed = x * mask3 straight from registers (streaming) ----
    #pragma unroll
    for (int k = 0; k < 4; k++) {
        const float m = m3[k];
        float4 a = make_float4(v[k][0] * m, v[k][1] * m, v[k][2] * m, v[k][3] * m);
        float4 b = make_float4(v[k][4] * m, v[k][5] * m, v[k][6] * m, v[k][7] * m);
        float4* orow = comp4 + (size_t)(base + t0 + k) * (DIMS / 4);
        __stcs(orow + lane, a);
        __stcs(orow + 32 + lane, b);
    }
}

extern "C" void kernel_launch(void* const* d_in, const int* in_sizes, int n_in,
                              void* d_out, int out_size)
{
    const float* x = (const float*)d_in[0];
    const int total = in_sizes[0];       // N * 256
    const int N  = total / DIMS;
    const int nw = N / WIN;
    float* out = (float*)d_out;

    float* mask_out;
    float* comp_out;
    if (out_size == N + total) {         // [mask1 (N) | compressed (N*D)]
        mask_out = out;
        comp_out = out + N;
    } else {                             // only compressed fits -> mask to scratch
        float* scratch;
        cudaGetSymbolAddress((void**)&scratch, g_mask_scratch);
        mask_out = scratch;
        comp_out = out;
    }

    focus_kernel<<<nw, 256>>>((const float4*)x, mask_out, (float4*)comp_out);
}